// round 3
// baseline (speedup 1.0000x reference)
#include <cuda_runtime.h>

#define FULL 0xFFFFFFFFu
#define NEGV -1e9f
#define NBLOCKS 2048
#define WPB 8               // warps per block (256 threads)
#define NWARPS (NBLOCKS * WPB)

__device__ float g_partial[NBLOCKS];
__device__ int   g_pcount[NBLOCKS];

__global__ __launch_bounds__(256, 8)
void kl_rows_kernel(const float* __restrict__ scores,
                    const int*   __restrict__ rankings,
                    const int*   __restrict__ mask,
                    int B)
{
    __shared__ float q_s[WPB][32];   // p scattered by rank position
    __shared__ float l_s[WPB][32];   // log(p+eps) scattered by index-compaction position
    __shared__ float racc[WPB];
    __shared__ int   rcnt[WPB];

    const int lane   = threadIdx.x & 31;
    const int wlocal = threadIdx.x >> 5;
    const int gw     = blockIdx.x * WPB + wlocal;
    const unsigned ltmask = (1u << lane) - 1u;

    float acc  = 0.0f;
    int   cacc = 0;

    for (int row = gw; row < B; row += NWARPS) {
        const int idx = (row << 5) | lane;
        const float sc = scores[idx];
        const int   rk = rankings[idx];
        const int   mk = mask[idx];

        const bool valid = (mk != 0) & (rk > 0);
        const unsigned vm = __ballot_sync(FULL, valid);
        const int nv = __popc(vm);

        const float s = valid ? sc : NEGV;

        // warp max
        float mx = s;
        #pragma unroll
        for (int d = 16; d; d >>= 1) mx = fmaxf(mx, __shfl_xor_sync(FULL, mx, d));

        // exp: invalid lanes get exp(-1e9 - mx) -> underflows to exactly 0
        const float e = __expf(s - mx);
        float S = e;
        #pragma unroll
        for (int d = 16; d; d >>= 1) S += __shfl_xor_sync(FULL, S, d);

        const float p   = __fdividef(e, S);
        const float lnS = __logf(S);
        const float lp  = (s - mx) - lnS;          // log softmax (valid lanes)
        const float lpr = __logf(p + 1e-8f);       // log(pred + eps)

        // ---- stable rank among valid lanes by (ranking asc, lane asc) ----
        // rankings in [1,32] -> 5-bit value v = rk-1. MSB-first radix rank via ballots.
        const int v = rk - 1;
        unsigned E = vm;                            // candidates with equal high bits, valid only
        int cnt = 0;
        #pragma unroll
        for (int k = 4; k >= 0; --k) {
            const bool mb = (v >> k) & 1;
            const unsigned bk = __ballot_sync(FULL, mb);
            if (mb) cnt += __popc(E & ~bk);
            E &= mb ? bk : ~bk;
        }
        const int rnk = cnt + __popc(E & ltmask);   // stable tie-break by lane
        const int pos = __popc(vm & ltmask);        // compaction position (valid-first, index order)

        // scatter p by rank, log(p+eps) by position (only valid lanes, both are
        // bijections onto [0, nv))
        if (valid) {
            q_s[wlocal][rnk] = p;
            l_s[wlocal][pos] = lpr;
        }
        __syncwarp();
        const float t2 = (lane < nv) ? q_s[wlocal][lane] * l_s[wlocal][lane] : 0.0f;
        __syncwarp();   // protect smem before next iteration's stores

        const float t1 = valid ? p * lp : 0.0f;     // q*log(q) contribution

        const bool ok = nv > 1;                     // rows with <=1 valid are skipped
        acc  += ok ? (t1 - t2) : 0.0f;
        cacc += (ok && lane == 0) ? 1 : 0;
    }

    // warp reduce accumulators
    #pragma unroll
    for (int d = 16; d; d >>= 1) {
        acc  += __shfl_xor_sync(FULL, acc, d);
        cacc += __shfl_xor_sync(FULL, cacc, d);
    }
    if (lane == 0) { racc[wlocal] = acc; rcnt[wlocal] = cacc; }
    __syncthreads();
    if (threadIdx.x == 0) {
        float a = 0.0f; int c = 0;
        #pragma unroll
        for (int i = 0; i < WPB; i++) { a += racc[i]; c += rcnt[i]; }
        g_partial[blockIdx.x] = a;
        g_pcount[blockIdx.x]  = c;
    }
}

__global__ void kl_finalize_kernel(float* __restrict__ out)
{
    __shared__ float sa[256];
    __shared__ int   sc[256];
    float a = 0.0f; int c = 0;
    for (int i = threadIdx.x; i < NBLOCKS; i += 256) {
        a += g_partial[i];
        c += g_pcount[i];
    }
    sa[threadIdx.x] = a; sc[threadIdx.x] = c;
    __syncthreads();
    #pragma unroll
    for (int s = 128; s; s >>= 1) {
        if (threadIdx.x < s) {
            sa[threadIdx.x] += sa[threadIdx.x + s];
            sc[threadIdx.x] += sc[threadIdx.x + s];
        }
        __syncthreads();
    }
    if (threadIdx.x == 0) {
        const int cc = sc[0] > 0 ? sc[0] : 1;
        out[0] = sa[0] / (float)cc;
    }
}

extern "C" void kernel_launch(void* const* d_in, const int* in_sizes, int n_in,
                              void* d_out, int out_size)
{
    const float* scores   = (const float*)d_in[0];
    const int*   rankings = (const int*)d_in[1];
    const int*   mask     = (const int*)d_in[2];
    float*       out      = (float*)d_out;

    const int B = in_sizes[0] / 32;   // H = 32

    kl_rows_kernel<<<NBLOCKS, 256>>>(scores, rankings, mask, B);
    kl_finalize_kernel<<<1, 256>>>(out);
}